// round 6
// baseline (speedup 1.0000x reference)
#include <cuda_runtime.h>
#include <cstdint>

// ---------------------------------------------------------------------------
// GCN, 4 layers + heads. R6 = R4 compute path (fp32 activations, tf32 MMA)
// + merged setup kernels (scan+norm+headprep, fill+scale).
// ---------------------------------------------------------------------------

constexpr int NN = 50000;
constexpr int NE = 800000;

__device__ int    g_outdeg[NN];
__device__ int    g_indeg[NN];
__device__ __align__(256) float  g_nsrc[NN];
__device__ __align__(256) float  g_ndst[NN];
__device__ int    g_rowptr[NN + 1];
__device__ int    g_cursor[NN];
__device__ __align__(256) int    g_esrc[NE];
__device__ __align__(256) float  g_hs[(size_t)NN * 128];   // activations (gather source)
__device__ __align__(256) float  g_agg[(size_t)NN * 128];  // aggregated * norm_dst
__device__ __align__(256) float2 g_zz[NN];                 // (z, z2) per node
__device__ float  g_q[128];                 // W3 @ Wp
__device__ float  g_q2[128];                // W3 @ Wv
__device__ float  g_cPI;

__device__ __forceinline__ uint32_t f2tf32(float x) {
    uint32_t r; asm("cvt.rna.tf32.f32 %0, %1;" : "=r"(r) : "f"(x)); return r;
}

__device__ __forceinline__ void mma_tf32(float* c, const uint32_t* a,
                                         uint32_t b0, uint32_t b1) {
    asm("mma.sync.aligned.m16n8k8.row.col.f32.tf32.tf32.f32 "
        "{%0,%1,%2,%3},{%4,%5,%6,%7},{%8,%9},{%0,%1,%2,%3};"
        : "+f"(c[0]), "+f"(c[1]), "+f"(c[2]), "+f"(c[3])
        : "r"(a[0]), "r"(a[1]), "r"(a[2]), "r"(a[3]), "r"(b0), "r"(b1));
}

// --------------------------- setup ----------------------------------------

__global__ void k_zero() {
    int i = blockIdx.x * blockDim.x + threadIdx.x;
    if (i < NN) { g_outdeg[i] = 0; g_indeg[i] = 0; }
}

__global__ void k_hist(const int* __restrict__ src, const int* __restrict__ dst) {
    int e = blockIdx.x * blockDim.x + threadIdx.x;
    if (e < NE) {
        atomicAdd(&g_outdeg[src[e]], 1);
        atomicAdd(&g_indeg[dst[e]], 1);
    }
}

// Single block: scan in-degrees -> rowptr/cursor, norms, head precompute.
__global__ void k_scan(const float* __restrict__ W3, const float* __restrict__ b3,
                       const float* __restrict__ Wp, const float* __restrict__ bp,
                       const float* __restrict__ Wv, const float* __restrict__ bv,
                       float* __restrict__ out) {
    constexpr int CH = (NN + 1023) / 1024;   // 49
    __shared__ int ts[1024];
    int t = threadIdx.x;
    int base = t * CH;
    int s = 0;
    for (int i = 0; i < CH; i++) {
        int idx = base + i;
        int v = (idx < NN) ? g_indeg[idx] : 0;
        if (idx < NN) g_rowptr[idx] = s;
        s += v;
    }
    ts[t] = s;
    __syncthreads();
    for (int off = 1; off < 1024; off <<= 1) {
        int v = (t >= off) ? ts[t - off] : 0;
        __syncthreads();
        ts[t] += v;
        __syncthreads();
    }
    int offset = ts[t] - s;
    for (int i = 0; i < CH; i++) {
        int idx = base + i;
        if (idx < NN) {
            int p = g_rowptr[idx] + offset;
            g_rowptr[idx] = p;
            g_cursor[idx] = p;
            g_nsrc[idx] = rsqrtf((float)max(g_outdeg[idx], 1));
            g_ndst[idx] = rsqrtf((float)max(g_indeg[idx], 1));
        }
    }
    if (t == 1023) g_rowptr[NN] = ts[1023];

    if (t < 128) {
        float a = 0.f, c = 0.f;
        for (int j = 0; j < 64; j++) {
            float w = W3[t * 64 + j];
            a += w * Wp[j];
            c += w * Wv[j];
        }
        g_q[t] = a;
        g_q2[t] = c;
        if (t == 0) {
            float cp = 0.f, cv = 0.f;
            for (int j = 0; j < 64; j++) { cp += b3[j] * Wp[j]; cv += b3[j] * Wv[j]; }
            g_cPI = cp + bp[0];
            out[NN] = (float)NN * cv + bv[0];
        }
    }
}

// fill CSR + scale features into hs, one kernel (disjoint index ranges)
__global__ void k_fillscale(const int* __restrict__ src, const int* __restrict__ dst,
                            const float* __restrict__ feats) {
    int i = blockIdx.x * blockDim.x + threadIdx.x;
    if (i < NE) {
        int p = atomicAdd(&g_cursor[dst[i]], 1);
        g_esrc[p] = src[i];
    } else {
        int j = i - NE;                    // 0 .. NN*32-1 (float4 index)
        if (j < NN * 32) {
            int node = j >> 5;
            float s = g_nsrc[node];
            float4 x = ((const float4*)feats)[j];
            x.x *= s; x.y *= s; x.z *= s; x.w *= s;
            ((float4*)g_hs)[j] = x;
        }
    }
}

// --------------------------- aggregation (R4 form) -------------------------

__global__ void k_agg() {
    int v = blockIdx.x * (blockDim.x >> 5) + (threadIdx.x >> 5);
    if (v >= NN) return;
    int lane = threadIdx.x & 31;
    int beg = g_rowptr[v], end = g_rowptr[v + 1];
    const float4* hs4 = (const float4*)g_hs;
    float4 a0 = make_float4(0.f, 0.f, 0.f, 0.f);
    float4 a1 = a0, a2 = a0, a3 = a0;
    int e = beg;
    for (; e + 3 < end; e += 4) {
        int u0 = g_esrc[e],     u1 = g_esrc[e + 1];
        int u2 = g_esrc[e + 2], u3 = g_esrc[e + 3];
        float4 x0 = hs4[u0 * 32 + lane];
        float4 x1 = hs4[u1 * 32 + lane];
        float4 x2 = hs4[u2 * 32 + lane];
        float4 x3 = hs4[u3 * 32 + lane];
        a0.x += x0.x; a0.y += x0.y; a0.z += x0.z; a0.w += x0.w;
        a1.x += x1.x; a1.y += x1.y; a1.z += x1.z; a1.w += x1.w;
        a2.x += x2.x; a2.y += x2.y; a2.z += x2.z; a2.w += x2.w;
        a3.x += x3.x; a3.y += x3.y; a3.z += x3.z; a3.w += x3.w;
    }
    for (; e < end; e++) {
        int u = g_esrc[e];
        float4 x = hs4[u * 32 + lane];
        a0.x += x.x; a0.y += x.y; a0.z += x.z; a0.w += x.w;
    }
    float nd = g_ndst[v];
    float4 o;
    o.x = ((a0.x + a1.x) + (a2.x + a3.x)) * nd;
    o.y = ((a0.y + a1.y) + (a2.y + a3.y)) * nd;
    o.z = ((a0.z + a1.z) + (a2.z + a3.z)) * nd;
    o.w = ((a0.w + a1.w) + (a2.w + a3.w)) * nd;
    ((float4*)g_agg)[v * 32 + lane] = o;
}

// --------------------------- tensor-core GEMM (R4 form) --------------------

constexpr int PADA = 132;
constexpr int PADW = 136;
constexpr int GEMM_SMEM = (128 * PADA + 128 * PADW) * 4;   // 137216 B

__global__ void __launch_bounds__(256) k_gemm(const float* __restrict__ W,
                                              const float* __restrict__ b) {
    extern __shared__ uint32_t sm[];
    uint32_t* sA = sm;                 // [row][k] tf32 bits, stride PADA
    uint32_t* sW = sm + 128 * PADA;    // [k][n]  tf32 bits, stride PADW

    int tid  = threadIdx.x;
    int lane = tid & 31;
    int warp = tid >> 5;
    int row0 = blockIdx.x * 128;

    const float4* A4 = (const float4*)g_agg;
    #pragma unroll
    for (int it = 0; it < 16; it++) {
        int i  = it * 256 + tid;
        int r  = i >> 5;
        int c4 = i & 31;
        int gr = row0 + r;
        float4 v = (gr < NN) ? A4[gr * 32 + c4] : make_float4(0.f, 0.f, 0.f, 0.f);
        uint4 t = make_uint4(f2tf32(v.x), f2tf32(v.y), f2tf32(v.z), f2tf32(v.w));
        *(uint4*)&sA[r * PADA + c4 * 4] = t;
    }
    const float4* W4 = (const float4*)W;
    #pragma unroll
    for (int it = 0; it < 16; it++) {
        int i  = it * 256 + tid;
        int k  = i >> 5;
        int c4 = i & 31;
        float4 v = W4[k * 32 + c4];
        uint4 t = make_uint4(f2tf32(v.x), f2tf32(v.y), f2tf32(v.z), f2tf32(v.w));
        *(uint4*)&sW[k * PADW + c4 * 4] = t;
    }
    __syncthreads();

    int wm = (warp >> 1) * 32;
    int wn = (warp & 1) * 64;

    float acc[2][8][4];
    #pragma unroll
    for (int mf = 0; mf < 2; mf++)
        #pragma unroll
        for (int nf = 0; nf < 8; nf++)
            #pragma unroll
            for (int j = 0; j < 4; j++) acc[mf][nf][j] = 0.f;

    int qr = lane >> 2;
    int qc = lane & 3;

    #pragma unroll
    for (int ks = 0; ks < 16; ks++) {
        int kb = ks * 8;
        uint32_t a[2][4];
        #pragma unroll
        for (int mf = 0; mf < 2; mf++) {
            int r = wm + mf * 16 + qr;
            a[mf][0] = sA[r * PADA + kb + qc];
            a[mf][1] = sA[(r + 8) * PADA + kb + qc];
            a[mf][2] = sA[r * PADA + kb + qc + 4];
            a[mf][3] = sA[(r + 8) * PADA + kb + qc + 4];
        }
        #pragma unroll
        for (int nf = 0; nf < 8; nf++) {
            int n = wn + nf * 8 + qr;
            uint32_t b0 = sW[(kb + qc) * PADW + n];
            uint32_t b1 = sW[(kb + qc + 4) * PADW + n];
            mma_tf32(acc[0][nf], a[0], b0, b1);
            mma_tf32(acc[1][nf], a[1], b0, b1);
        }
    }

    // epilogue: bias + relu + nsrc scale -> fp32 hs
    #pragma unroll
    for (int mf = 0; mf < 2; mf++) {
        int r0 = row0 + wm + mf * 16 + qr;
        int r1 = r0 + 8;
        float s0 = (r0 < NN) ? g_nsrc[r0] : 0.f;
        float s1 = (r1 < NN) ? g_nsrc[r1] : 0.f;
        #pragma unroll
        for (int nf = 0; nf < 8; nf++) {
            int c = wn + nf * 8 + qc * 2;
            float2 bb = *(const float2*)&b[c];
            if (r0 < NN) {
                float2 o;
                o.x = fmaxf(acc[mf][nf][0] + bb.x, 0.f) * s0;
                o.y = fmaxf(acc[mf][nf][1] + bb.y, 0.f) * s0;
                *(float2*)&g_hs[(size_t)r0 * 128 + c] = o;
            }
            if (r1 < NN) {
                float2 o;
                o.x = fmaxf(acc[mf][nf][2] + bb.x, 0.f) * s1;
                o.y = fmaxf(acc[mf][nf][3] + bb.y, 0.f) * s1;
                *(float2*)&g_hs[(size_t)r1 * 128 + c] = o;
            }
        }
    }
}

// ---------------------- collapsed layer 3 + heads --------------------------

__global__ void k_z() {
    int v = blockIdx.x * (blockDim.x >> 5) + (threadIdx.x >> 5);
    if (v >= NN) return;
    int lane = threadIdx.x & 31;
    float4 h = ((const float4*)g_hs)[v * 32 + lane];
    float4 q = ((const float4*)g_q)[lane];
    float4 q2 = ((const float4*)g_q2)[lane];
    float z  = h.x * q.x  + h.y * q.y  + h.z * q.z  + h.w * q.w;
    float z2 = h.x * q2.x + h.y * q2.y + h.z * q2.z + h.w * q2.w;
    #pragma unroll
    for (int off = 16; off; off >>= 1) {
        z  += __shfl_xor_sync(0xffffffff, z,  off);
        z2 += __shfl_xor_sync(0xffffffff, z2, off);
    }
    if (lane == 0) g_zz[v] = make_float2(z, z2);
}

__global__ void k_zagg(float* __restrict__ out) {
    __shared__ float red[256];
    int v = blockIdx.x * blockDim.x + threadIdx.x;
    float vp = 0.f;
    if (v < NN) {
        int beg = g_rowptr[v], end = g_rowptr[v + 1];
        float s0 = 0.f, s1 = 0.f, t0 = 0.f, t1 = 0.f;
        int e = beg;
        for (; e + 1 < end; e += 2) {
            float2 a = g_zz[g_esrc[e]];
            float2 b = g_zz[g_esrc[e + 1]];
            s0 += a.x; t0 += a.y;
            s1 += b.x; t1 += b.y;
        }
        if (e < end) {
            float2 a = g_zz[g_esrc[e]];
            s0 += a.x; t0 += a.y;
        }
        float nd = g_ndst[v];
        out[v] = nd * (s0 + s1) + g_cPI;
        vp = nd * (t0 + t1);
    }
    red[threadIdx.x] = vp;
    __syncthreads();
    for (int off = 128; off; off >>= 1) {
        if (threadIdx.x < off) red[threadIdx.x] += red[threadIdx.x + off];
        __syncthreads();
    }
    if (threadIdx.x == 0) atomicAdd(&out[NN], red[0]);
}

// --------------------------- launch ----------------------------------------

extern "C" void kernel_launch(void* const* d_in, const int* in_sizes, int n_in,
                              void* d_out, int out_size) {
    const float* feats = (const float*)d_in[0];
    const int*   src   = (const int*)d_in[1];
    const int*   dst   = (const int*)d_in[2];
    const float* W0 = (const float*)d_in[3];  const float* b0 = (const float*)d_in[4];
    const float* W1 = (const float*)d_in[5];  const float* b1 = (const float*)d_in[6];
    const float* W2 = (const float*)d_in[7];  const float* b2 = (const float*)d_in[8];
    const float* W3 = (const float*)d_in[9];  const float* b3 = (const float*)d_in[10];
    const float* Wp = (const float*)d_in[11]; const float* bp = (const float*)d_in[12];
    const float* Wv = (const float*)d_in[13]; const float* bv = (const float*)d_in[14];
    float* out = (float*)d_out;

    cudaFuncSetAttribute(k_gemm, cudaFuncAttributeMaxDynamicSharedMemorySize,
                         GEMM_SMEM);

    k_zero<<<(NN + 255) / 256, 256>>>();
    k_hist<<<(NE + 255) / 256, 256>>>(src, dst);
    k_scan<<<1, 1024>>>(W3, b3, Wp, bp, Wv, bv, out);
    k_fillscale<<<(NE + NN * 32 + 255) / 256, 256>>>(src, dst, feats);

    const int aggGrid  = (NN + 7) / 8;        // 8 warps/block
    const int gemmGrid = (NN + 127) / 128;    // 391

    k_agg<<<aggGrid, 256>>>();
    k_gemm<<<gemmGrid, 256, GEMM_SMEM>>>(W0, b0);
    k_agg<<<aggGrid, 256>>>();
    k_gemm<<<gemmGrid, 256, GEMM_SMEM>>>(W1, b1);
    k_agg<<<aggGrid, 256>>>();
    k_gemm<<<gemmGrid, 256, GEMM_SMEM>>>(W2, b2);

    k_z<<<aggGrid, 256>>>();
    k_zagg<<<(NN + 255) / 256, 256>>>(out);
}

// round 7
// speedup vs baseline: 1.3250x; 1.3250x over previous
#include <cuda_runtime.h>
#include <cstdint>

// ---------------------------------------------------------------------------
// GCN, 4 layers + heads. R7 = exact R4 structure; single change:
// layer-0 aggregation gathers feats[u]*nsrc[u] directly (k_scale0 deleted).
// ---------------------------------------------------------------------------

constexpr int NN = 50000;
constexpr int NE = 800000;
constexpr int F  = 128;

__device__ int    g_outdeg[NN];
__device__ int    g_indeg[NN];
__device__ float  g_nsrc[NN];
__device__ float  g_ndst[NN];
__device__ int    g_rowptr[NN + 1];
__device__ int    g_cursor[NN];
__device__ int    g_esrc[NE];
__device__ float  g_hs[(size_t)NN * F];    // activations (gather source, layers 1+)
__device__ float  g_agg[(size_t)NN * F];   // aggregated * norm_dst (GEMM input)
__device__ float2 g_zz[NN];                // (z, z2) per node
__device__ float  g_q[F];                  // W3 @ Wp
__device__ float  g_q2[F];                 // W3 @ Wv
__device__ float  g_cPI;

__device__ __forceinline__ uint32_t f2tf32(float x) {
    uint32_t r; asm("cvt.rna.tf32.f32 %0, %1;" : "=r"(r) : "f"(x)); return r;
}

__device__ __forceinline__ void mma_tf32(float* c, const uint32_t* a,
                                         uint32_t b0, uint32_t b1) {
    asm("mma.sync.aligned.m16n8k8.row.col.f32.tf32.tf32.f32 "
        "{%0,%1,%2,%3},{%4,%5,%6,%7},{%8,%9},{%0,%1,%2,%3};"
        : "+f"(c[0]), "+f"(c[1]), "+f"(c[2]), "+f"(c[3])
        : "r"(a[0]), "r"(a[1]), "r"(a[2]), "r"(a[3]), "r"(b0), "r"(b1));
}

// --------------------------- setup ----------------------------------------

__global__ void k_zero() {
    int i = blockIdx.x * blockDim.x + threadIdx.x;
    if (i < NN) { g_outdeg[i] = 0; g_indeg[i] = 0; }
}

__global__ void k_hist(const int* __restrict__ src, const int* __restrict__ dst) {
    int e = blockIdx.x * blockDim.x + threadIdx.x;
    if (e < NE) {
        atomicAdd(&g_outdeg[src[e]], 1);
        atomicAdd(&g_indeg[dst[e]], 1);
    }
}

// Single-block scan: per-thread chunk of 49 + one 1024-wide block scan.
__global__ void k_scan() {
    constexpr int CH = (NN + 1023) / 1024;   // 49
    __shared__ int ts[1024];
    int t = threadIdx.x;
    int base = t * CH;
    int s = 0;
    for (int i = 0; i < CH; i++) {
        int idx = base + i;
        int v = (idx < NN) ? g_indeg[idx] : 0;
        if (idx < NN) g_rowptr[idx] = s;
        s += v;
    }
    ts[t] = s;
    __syncthreads();
    for (int off = 1; off < 1024; off <<= 1) {
        int v = (t >= off) ? ts[t - off] : 0;
        __syncthreads();
        ts[t] += v;
        __syncthreads();
    }
    int offset = ts[t] - s;
    for (int i = 0; i < CH; i++) {
        int idx = base + i;
        if (idx < NN) {
            int p = g_rowptr[idx] + offset;
            g_rowptr[idx] = p;
            g_cursor[idx] = p;
        }
    }
    if (t == 1023) g_rowptr[NN] = ts[1023];
}

__global__ void k_norm() {
    int i = blockIdx.x * blockDim.x + threadIdx.x;
    if (i < NN) {
        g_nsrc[i] = rsqrtf((float)max(g_outdeg[i], 1));
        g_ndst[i] = rsqrtf((float)max(g_indeg[i], 1));
    }
}

__global__ void k_fill(const int* __restrict__ src, const int* __restrict__ dst) {
    int e = blockIdx.x * blockDim.x + threadIdx.x;
    if (e < NE) {
        int p = atomicAdd(&g_cursor[dst[e]], 1);
        g_esrc[p] = src[e];
    }
}

__global__ void k_prep(const float* __restrict__ W3, const float* __restrict__ b3,
                       const float* __restrict__ Wp, const float* __restrict__ bp,
                       const float* __restrict__ Wv, const float* __restrict__ bv,
                       float* __restrict__ out) {
    int k = threadIdx.x;   // 128 threads
    float a = 0.f, c = 0.f;
    for (int j = 0; j < 64; j++) {
        float w = W3[k * 64 + j];
        a += w * Wp[j];
        c += w * Wv[j];
    }
    g_q[k] = a;
    g_q2[k] = c;
    if (k == 0) {
        float cp = 0.f, cv = 0.f;
        for (int j = 0; j < 64; j++) { cp += b3[j] * Wp[j]; cv += b3[j] * Wv[j]; }
        g_cPI = cp + bp[0];
        out[NN] = (float)NN * cv + bv[0];
    }
}

// --------------------------- aggregation ----------------------------------
// One warp per node; lane owns one float4. FIRST variant gathers from feats
// and multiplies by warp-uniform nsrc[u] (broadcast load).

template <bool FIRST>
__global__ void k_agg(const float* __restrict__ feats) {
    int v = blockIdx.x * (blockDim.x >> 5) + (threadIdx.x >> 5);
    if (v >= NN) return;
    int lane = threadIdx.x & 31;
    int beg = g_rowptr[v], end = g_rowptr[v + 1];
    const float4* hs4 = FIRST ? (const float4*)feats : (const float4*)g_hs;
    float4 a0 = make_float4(0.f, 0.f, 0.f, 0.f);
    float4 a1 = a0, a2 = a0, a3 = a0;
    int e = beg;
    for (; e + 3 < end; e += 4) {
        int u0 = g_esrc[e],     u1 = g_esrc[e + 1];
        int u2 = g_esrc[e + 2], u3 = g_esrc[e + 3];
        float4 x0 = hs4[u0 * 32 + lane];
        float4 x1 = hs4[u1 * 32 + lane];
        float4 x2 = hs4[u2 * 32 + lane];
        float4 x3 = hs4[u3 * 32 + lane];
        if (FIRST) {
            float s0 = g_nsrc[u0], s1 = g_nsrc[u1];
            float s2 = g_nsrc[u2], s3 = g_nsrc[u3];
            a0.x = fmaf(x0.x, s0, a0.x); a0.y = fmaf(x0.y, s0, a0.y);
            a0.z = fmaf(x0.z, s0, a0.z); a0.w = fmaf(x0.w, s0, a0.w);
            a1.x = fmaf(x1.x, s1, a1.x); a1.y = fmaf(x1.y, s1, a1.y);
            a1.z = fmaf(x1.z, s1, a1.z); a1.w = fmaf(x1.w, s1, a1.w);
            a2.x = fmaf(x2.x, s2, a2.x); a2.y = fmaf(x2.y, s2, a2.y);
            a2.z = fmaf(x2.z, s2, a2.z); a2.w = fmaf(x2.w, s2, a2.w);
            a3.x = fmaf(x3.x, s3, a3.x); a3.y = fmaf(x3.y, s3, a3.y);
            a3.z = fmaf(x3.z, s3, a3.z); a3.w = fmaf(x3.w, s3, a3.w);
        } else {
            a0.x += x0.x; a0.y += x0.y; a0.z += x0.z; a0.w += x0.w;
            a1.x += x1.x; a1.y += x1.y; a1.z += x1.z; a1.w += x1.w;
            a2.x += x2.x; a2.y += x2.y; a2.z += x2.z; a2.w += x2.w;
            a3.x += x3.x; a3.y += x3.y; a3.z += x3.z; a3.w += x3.w;
        }
    }
    for (; e < end; e++) {
        int u = g_esrc[e];
        float4 x = hs4[u * 32 + lane];
        if (FIRST) {
            float s = g_nsrc[u];
            a0.x = fmaf(x.x, s, a0.x); a0.y = fmaf(x.y, s, a0.y);
            a0.z = fmaf(x.z, s, a0.z); a0.w = fmaf(x.w, s, a0.w);
        } else {
            a0.x += x.x; a0.y += x.y; a0.z += x.z; a0.w += x.w;
        }
    }
    float nd = g_ndst[v];
    float4 o;
    o.x = ((a0.x + a1.x) + (a2.x + a3.x)) * nd;
    o.y = ((a0.y + a1.y) + (a2.y + a3.y)) * nd;
    o.z = ((a0.z + a1.z) + (a2.z + a3.z)) * nd;
    o.w = ((a0.w + a1.w) + (a2.w + a3.w)) * nd;
    ((float4*)g_agg)[v * 32 + lane] = o;
}

// --------------------------- tensor-core GEMM (R4 form) --------------------

constexpr int PADA = 132;
constexpr int PADW = 136;
constexpr int GEMM_SMEM = (128 * PADA + 128 * PADW) * 4;   // 137216 B

__global__ void __launch_bounds__(256) k_gemm(const float* __restrict__ W,
                                              const float* __restrict__ b) {
    extern __shared__ uint32_t sm[];
    uint32_t* sA = sm;                 // [row][k] tf32 bits, stride PADA
    uint32_t* sW = sm + 128 * PADA;    // [k][n]  tf32 bits, stride PADW

    int tid  = threadIdx.x;
    int lane = tid & 31;
    int warp = tid >> 5;
    int row0 = blockIdx.x * 128;

    const float4* A4 = (const float4*)g_agg;
    #pragma unroll
    for (int it = 0; it < 16; it++) {
        int i  = it * 256 + tid;
        int r  = i >> 5;
        int c4 = i & 31;
        int gr = row0 + r;
        float4 v = (gr < NN) ? A4[gr * 32 + c4] : make_float4(0.f, 0.f, 0.f, 0.f);
        uint4 t = make_uint4(f2tf32(v.x), f2tf32(v.y), f2tf32(v.z), f2tf32(v.w));
        *(uint4*)&sA[r * PADA + c4 * 4] = t;
    }
    const float4* W4 = (const float4*)W;
    #pragma unroll
    for (int it = 0; it < 16; it++) {
        int i  = it * 256 + tid;
        int k  = i >> 5;
        int c4 = i & 31;
        float4 v = W4[k * 32 + c4];
        uint4 t = make_uint4(f2tf32(v.x), f2tf32(v.y), f2tf32(v.z), f2tf32(v.w));
        *(uint4*)&sW[k * PADW + c4 * 4] = t;
    }
    __syncthreads();

    int wm = (warp >> 1) * 32;
    int wn = (warp & 1) * 64;

    float acc[2][8][4];
    #pragma unroll
    for (int mf = 0; mf < 2; mf++)
        #pragma unroll
        for (int nf = 0; nf < 8; nf++)
            #pragma unroll
            for (int j = 0; j < 4; j++) acc[mf][nf][j] = 0.f;

    int qr = lane >> 2;
    int qc = lane & 3;

    #pragma unroll
    for (int ks = 0; ks < 16; ks++) {
        int kb = ks * 8;
        uint32_t a[2][4];
        #pragma unroll
        for (int mf = 0; mf < 2; mf++) {
            int r = wm + mf * 16 + qr;
            a[mf][0] = sA[r * PADA + kb + qc];
            a[mf][1] = sA[(r + 8) * PADA + kb + qc];
            a[mf][2] = sA[r * PADA + kb + qc + 4];
            a[mf][3] = sA[(r + 8) * PADA + kb + qc + 4];
        }
        #pragma unroll
        for (int nf = 0; nf < 8; nf++) {
            int n = wn + nf * 8 + qr;
            uint32_t b0 = sW[(kb + qc) * PADW + n];
            uint32_t b1 = sW[(kb + qc + 4) * PADW + n];
            mma_tf32(acc[0][nf], a[0], b0, b1);
            mma_tf32(acc[1][nf], a[1], b0, b1);
        }
    }

    #pragma unroll
    for (int mf = 0; mf < 2; mf++) {
        int r0 = row0 + wm + mf * 16 + qr;
        int r1 = r0 + 8;
        float s0 = (r0 < NN) ? g_nsrc[r0] : 0.f;
        float s1 = (r1 < NN) ? g_nsrc[r1] : 0.f;
        #pragma unroll
        for (int nf = 0; nf < 8; nf++) {
            int c = wn + nf * 8 + qc * 2;
            float2 bb = *(const float2*)&b[c];
            if (r0 < NN) {
                float2 o;
                o.x = fmaxf(acc[mf][nf][0] + bb.x, 0.f) * s0;
                o.y = fmaxf(acc[mf][nf][1] + bb.y, 0.f) * s0;
                *(float2*)&g_hs[(size_t)r0 * 128 + c] = o;
            }
            if (r1 < NN) {
                float2 o;
                o.x = fmaxf(acc[mf][nf][2] + bb.x, 0.f) * s1;
                o.y = fmaxf(acc[mf][nf][3] + bb.y, 0.f) * s1;
                *(float2*)&g_hs[(size_t)r1 * 128 + c] = o;
            }
        }
    }
}

// ---------------------- collapsed layer 3 + heads --------------------------

__global__ void k_z() {
    int v = blockIdx.x * (blockDim.x >> 5) + (threadIdx.x >> 5);
    if (v >= NN) return;
    int lane = threadIdx.x & 31;
    float4 h = ((const float4*)g_hs)[v * 32 + lane];
    float4 q = ((const float4*)g_q)[lane];
    float4 q2 = ((const float4*)g_q2)[lane];
    float z  = h.x * q.x  + h.y * q.y  + h.z * q.z  + h.w * q.w;
    float z2 = h.x * q2.x + h.y * q2.y + h.z * q2.z + h.w * q2.w;
    #pragma unroll
    for (int off = 16; off; off >>= 1) {
        z  += __shfl_xor_sync(0xffffffff, z,  off);
        z2 += __shfl_xor_sync(0xffffffff, z2, off);
    }
    if (lane == 0) g_zz[v] = make_float2(z, z2);
}

__global__ void k_zagg(float* __restrict__ out) {
    __shared__ float red[256];
    int v = blockIdx.x * blockDim.x + threadIdx.x;
    float vp = 0.f;
    if (v < NN) {
        int beg = g_rowptr[v], end = g_rowptr[v + 1];
        float s0 = 0.f, s1 = 0.f, t0 = 0.f, t1 = 0.f;
        int e = beg;
        for (; e + 1 < end; e += 2) {
            float2 a = g_zz[g_esrc[e]];
            float2 b = g_zz[g_esrc[e + 1]];
            s0 += a.x; t0 += a.y;
            s1 += b.x; t1 += b.y;
        }
        if (e < end) {
            float2 a = g_zz[g_esrc[e]];
            s0 += a.x; t0 += a.y;
        }
        float nd = g_ndst[v];
        out[v] = nd * (s0 + s1) + g_cPI;
        vp = nd * (t0 + t1);
    }
    red[threadIdx.x] = vp;
    __syncthreads();
    for (int off = 128; off; off >>= 1) {
        if (threadIdx.x < off) red[threadIdx.x] += red[threadIdx.x + off];
        __syncthreads();
    }
    if (threadIdx.x == 0) atomicAdd(&out[NN], red[0]);
}

// --------------------------- launch ----------------------------------------

extern "C" void kernel_launch(void* const* d_in, const int* in_sizes, int n_in,
                              void* d_out, int out_size) {
    const float* feats = (const float*)d_in[0];
    const int*   src   = (const int*)d_in[1];
    const int*   dst   = (const int*)d_in[2];
    const float* W0 = (const float*)d_in[3];  const float* b0 = (const float*)d_in[4];
    const float* W1 = (const float*)d_in[5];  const float* b1 = (const float*)d_in[6];
    const float* W2 = (const float*)d_in[7];  const float* b2 = (const float*)d_in[8];
    const float* W3 = (const float*)d_in[9];  const float* b3 = (const float*)d_in[10];
    const float* Wp = (const float*)d_in[11]; const float* bp = (const float*)d_in[12];
    const float* Wv = (const float*)d_in[13]; const float* bv = (const float*)d_in[14];
    float* out = (float*)d_out;

    cudaFuncSetAttribute(k_gemm, cudaFuncAttributeMaxDynamicSharedMemorySize,
                         GEMM_SMEM);

    k_zero<<<(NN + 255) / 256, 256>>>();
    k_hist<<<(NE + 255) / 256, 256>>>(src, dst);
    k_scan<<<1, 1024>>>();
    k_norm<<<(NN + 255) / 256, 256>>>();
    k_fill<<<(NE + 255) / 256, 256>>>(src, dst);
    k_prep<<<1, 128>>>(W3, b3, Wp, bp, Wv, bv, out);

    const int aggGrid  = (NN + 7) / 8;        // 8 warps/block
    const int gemmGrid = (NN + 127) / 128;    // 391

    k_agg<true><<<aggGrid, 256>>>(feats);
    k_gemm<<<gemmGrid, 256, GEMM_SMEM>>>(W0, b0);
    k_agg<false><<<aggGrid, 256>>>(feats);
    k_gemm<<<gemmGrid, 256, GEMM_SMEM>>>(W1, b1);
    k_agg<false><<<aggGrid, 256>>>(feats);
    k_gemm<<<gemmGrid, 256, GEMM_SMEM>>>(W2, b2);

    k_z<<<aggGrid, 256>>>();
    k_zagg<<<(NN + 255) / 256, 256>>>(out);
}

// round 8
// speedup vs baseline: 1.4474x; 1.0924x over previous
#include <cuda_runtime.h>
#include <cuda_fp16.h>
#include <cstdint>

// ---------------------------------------------------------------------------
// GCN, 4 layers + heads. R8 = R4/R7 structure (separate small kernels — the
// merged variants regressed twice); single change vs R7: activations g_hs
// stored fp16 (halves L2 gather traffic). Accumulation fp32, GEMM tf32.
// ---------------------------------------------------------------------------

constexpr int NN = 50000;
constexpr int NE = 800000;

__device__ int    g_outdeg[NN];
__device__ int    g_indeg[NN];
__device__ float  g_nsrc[NN];
__device__ float  g_ndst[NN];
__device__ int    g_rowptr[NN + 1];
__device__ int    g_cursor[NN];
__device__ int    g_esrc[NE];
__device__ uint2  g_hs[(size_t)NN * 32];    // fp16 activations: 32 x uint2 = 128 halves/node
__device__ float  g_agg[(size_t)NN * 128];  // aggregated * norm_dst (GEMM input, fp32)
__device__ float2 g_zz[NN];                 // (z, z2) per node
__device__ float  g_q[128];                 // W3 @ Wp
__device__ float  g_q2[128];                // W3 @ Wv
__device__ float  g_cPI;

__device__ __forceinline__ uint32_t f2tf32(float x) {
    uint32_t r; asm("cvt.rna.tf32.f32 %0, %1;" : "=r"(r) : "f"(x)); return r;
}

__device__ __forceinline__ void mma_tf32(float* c, const uint32_t* a,
                                         uint32_t b0, uint32_t b1) {
    asm("mma.sync.aligned.m16n8k8.row.col.f32.tf32.tf32.f32 "
        "{%0,%1,%2,%3},{%4,%5,%6,%7},{%8,%9},{%0,%1,%2,%3};"
        : "+f"(c[0]), "+f"(c[1]), "+f"(c[2]), "+f"(c[3])
        : "r"(a[0]), "r"(a[1]), "r"(a[2]), "r"(a[3]), "r"(b0), "r"(b1));
}

__device__ __forceinline__ uint2 pack4h(float4 v) {
    uint2 r;
    __half2 h0 = __floats2half2_rn(v.x, v.y);
    __half2 h1 = __floats2half2_rn(v.z, v.w);
    r.x = *(uint32_t*)&h0;
    r.y = *(uint32_t*)&h1;
    return r;
}
__device__ __forceinline__ float4 unpack4h(uint2 u) {
    __half2 h0 = *(__half2*)&u.x;
    __half2 h1 = *(__half2*)&u.y;
    float2 f0 = __half22float2(h0);
    float2 f1 = __half22float2(h1);
    return make_float4(f0.x, f0.y, f1.x, f1.y);
}

// --------------------------- setup ----------------------------------------

__global__ void k_zero() {
    int i = blockIdx.x * blockDim.x + threadIdx.x;
    if (i < NN) { g_outdeg[i] = 0; g_indeg[i] = 0; }
}

__global__ void k_hist(const int* __restrict__ src, const int* __restrict__ dst) {
    int e = blockIdx.x * blockDim.x + threadIdx.x;
    if (e < NE) {
        atomicAdd(&g_outdeg[src[e]], 1);
        atomicAdd(&g_indeg[dst[e]], 1);
    }
}

// Single-block scan: per-thread chunk of 49 + one 1024-wide block scan.
__global__ void k_scan() {
    constexpr int CH = (NN + 1023) / 1024;   // 49
    __shared__ int ts[1024];
    int t = threadIdx.x;
    int base = t * CH;
    int s = 0;
    for (int i = 0; i < CH; i++) {
        int idx = base + i;
        int v = (idx < NN) ? g_indeg[idx] : 0;
        if (idx < NN) g_rowptr[idx] = s;
        s += v;
    }
    ts[t] = s;
    __syncthreads();
    for (int off = 1; off < 1024; off <<= 1) {
        int v = (t >= off) ? ts[t - off] : 0;
        __syncthreads();
        ts[t] += v;
        __syncthreads();
    }
    int offset = ts[t] - s;
    for (int i = 0; i < CH; i++) {
        int idx = base + i;
        if (idx < NN) {
            int p = g_rowptr[idx] + offset;
            g_rowptr[idx] = p;
            g_cursor[idx] = p;
        }
    }
    if (t == 1023) g_rowptr[NN] = ts[1023];
}

__global__ void k_norm() {
    int i = blockIdx.x * blockDim.x + threadIdx.x;
    if (i < NN) {
        g_nsrc[i] = rsqrtf((float)max(g_outdeg[i], 1));
        g_ndst[i] = rsqrtf((float)max(g_indeg[i], 1));
    }
}

__global__ void k_fill(const int* __restrict__ src, const int* __restrict__ dst) {
    int e = blockIdx.x * blockDim.x + threadIdx.x;
    if (e < NE) {
        int p = atomicAdd(&g_cursor[dst[e]], 1);
        g_esrc[p] = src[e];
    }
}

// features * nsrc -> fp16 hs
__global__ void k_scale0(const float* __restrict__ feats) {
    int i = blockIdx.x * blockDim.x + threadIdx.x;   // float4 index
    constexpr int TOT = NN * 32;
    if (i < TOT) {
        int node = i >> 5;
        float s = g_nsrc[node];
        float4 x = ((const float4*)feats)[i];
        x.x *= s; x.y *= s; x.z *= s; x.w *= s;
        g_hs[i] = pack4h(x);
    }
}

__global__ void k_prep(const float* __restrict__ W3, const float* __restrict__ b3,
                       const float* __restrict__ Wp, const float* __restrict__ bp,
                       const float* __restrict__ Wv, const float* __restrict__ bv,
                       float* __restrict__ out) {
    int k = threadIdx.x;   // 128 threads
    float a = 0.f, c = 0.f;
    for (int j = 0; j < 64; j++) {
        float w = W3[k * 64 + j];
        a += w * Wp[j];
        c += w * Wv[j];
    }
    g_q[k] = a;
    g_q2[k] = c;
    if (k == 0) {
        float cp = 0.f, cv = 0.f;
        for (int j = 0; j < 64; j++) { cp += b3[j] * Wp[j]; cv += b3[j] * Wv[j]; }
        g_cPI = cp + bp[0];
        out[NN] = (float)NN * cv + bv[0];
    }
}

// --------------------------- aggregation ----------------------------------
// One warp per node; lane owns 4 feats (8B fp16). 8-deep edge unroll.

__global__ void k_agg() {
    int v = blockIdx.x * (blockDim.x >> 5) + (threadIdx.x >> 5);
    if (v >= NN) return;
    int lane = threadIdx.x & 31;
    int beg = g_rowptr[v], end = g_rowptr[v + 1];
    float4 a0 = make_float4(0.f, 0.f, 0.f, 0.f);
    float4 a1 = a0;
    int e = beg;
    for (; e + 7 < end; e += 8) {
        uint2 x[8];
        #pragma unroll
        for (int j = 0; j < 8; j++)
            x[j] = g_hs[(size_t)g_esrc[e + j] * 32 + lane];
        #pragma unroll
        for (int j = 0; j < 8; j += 2) {
            float4 f0 = unpack4h(x[j]);
            float4 f1 = unpack4h(x[j + 1]);
            a0.x += f0.x; a0.y += f0.y; a0.z += f0.z; a0.w += f0.w;
            a1.x += f1.x; a1.y += f1.y; a1.z += f1.z; a1.w += f1.w;
        }
    }
    for (; e < end; e++) {
        float4 f = unpack4h(g_hs[(size_t)g_esrc[e] * 32 + lane]);
        a0.x += f.x; a0.y += f.y; a0.z += f.z; a0.w += f.w;
    }
    float nd = g_ndst[v];
    float4 o;
    o.x = (a0.x + a1.x) * nd;
    o.y = (a0.y + a1.y) * nd;
    o.z = (a0.z + a1.z) * nd;
    o.w = (a0.w + a1.w) * nd;
    ((float4*)g_agg)[v * 32 + lane] = o;
}

// --------------------------- tensor-core GEMM ------------------------------
// g_hs = fp16(relu(g_agg @ W + b) * nsrc); W 128x128 row-major [k][n].

constexpr int PADA = 132;
constexpr int PADW = 136;
constexpr int GEMM_SMEM = (128 * PADA + 128 * PADW) * 4;   // 137216 B

__global__ void __launch_bounds__(256) k_gemm(const float* __restrict__ W,
                                              const float* __restrict__ b) {
    extern __shared__ uint32_t sm[];
    uint32_t* sA = sm;                 // [row][k] tf32 bits, stride PADA
    uint32_t* sW = sm + 128 * PADA;    // [k][n]  tf32 bits, stride PADW

    int tid  = threadIdx.x;
    int lane = tid & 31;
    int warp = tid >> 5;
    int row0 = blockIdx.x * 128;

    const float4* A4 = (const float4*)g_agg;
    #pragma unroll
    for (int it = 0; it < 16; it++) {
        int i  = it * 256 + tid;
        int r  = i >> 5;
        int c4 = i & 31;
        int gr = row0 + r;
        float4 v = (gr < NN) ? A4[gr * 32 + c4] : make_float4(0.f, 0.f, 0.f, 0.f);
        uint4 t = make_uint4(f2tf32(v.x), f2tf32(v.y), f2tf32(v.z), f2tf32(v.w));
        *(uint4*)&sA[r * PADA + c4 * 4] = t;
    }
    const float4* W4 = (const float4*)W;
    #pragma unroll
    for (int it = 0; it < 16; it++) {
        int i  = it * 256 + tid;
        int k  = i >> 5;
        int c4 = i & 31;
        float4 v = W4[k * 32 + c4];
        uint4 t = make_uint4(f2tf32(v.x), f2tf32(v.y), f2tf32(v.z), f2tf32(v.w));
        *(uint4*)&sW[k * PADW + c4 * 4] = t;
    }
    __syncthreads();

    int wm = (warp >> 1) * 32;
    int wn = (warp & 1) * 64;

    float acc[2][8][4];
    #pragma unroll
    for (int mf = 0; mf < 2; mf++)
        #pragma unroll
        for (int nf = 0; nf < 8; nf++)
            #pragma unroll
            for (int j = 0; j < 4; j++) acc[mf][nf][j] = 0.f;

    int qr = lane >> 2;
    int qc = lane & 3;

    #pragma unroll
    for (int ks = 0; ks < 16; ks++) {
        int kb = ks * 8;
        uint32_t a[2][4];
        #pragma unroll
        for (int mf = 0; mf < 2; mf++) {
            int r = wm + mf * 16 + qr;
            a[mf][0] = sA[r * PADA + kb + qc];
            a[mf][1] = sA[(r + 8) * PADA + kb + qc];
            a[mf][2] = sA[r * PADA + kb + qc + 4];
            a[mf][3] = sA[(r + 8) * PADA + kb + qc + 4];
        }
        #pragma unroll
        for (int nf = 0; nf < 8; nf++) {
            int n = wn + nf * 8 + qr;
            uint32_t b0 = sW[(kb + qc) * PADW + n];
            uint32_t b1 = sW[(kb + qc + 4) * PADW + n];
            mma_tf32(acc[0][nf], a[0], b0, b1);
            mma_tf32(acc[1][nf], a[1], b0, b1);
        }
    }

    // epilogue: bias + relu + nsrc scale -> fp16 hs
    #pragma unroll
    for (int mf = 0; mf < 2; mf++) {
        int r0 = row0 + wm + mf * 16 + qr;
        int r1 = r0 + 8;
        float s0 = (r0 < NN) ? g_nsrc[r0] : 0.f;
        float s1 = (r1 < NN) ? g_nsrc[r1] : 0.f;
        #pragma unroll
        for (int nf = 0; nf < 8; nf++) {
            int c = wn + nf * 8 + qc * 2;
            float2 bb = *(const float2*)&b[c];
            if (r0 < NN) {
                __half2 h = __floats2half2_rn(
                    fmaxf(acc[mf][nf][0] + bb.x, 0.f) * s0,
                    fmaxf(acc[mf][nf][1] + bb.y, 0.f) * s0);
                ((__half2*)g_hs)[(size_t)r0 * 64 + (c >> 1)] = h;
            }
            if (r1 < NN) {
                __half2 h = __floats2half2_rn(
                    fmaxf(acc[mf][nf][2] + bb.x, 0.f) * s1,
                    fmaxf(acc[mf][nf][3] + bb.y, 0.f) * s1);
                ((__half2*)g_hs)[(size_t)r1 * 64 + (c >> 1)] = h;
            }
        }
    }
}

// ---------------------- collapsed layer 3 + heads --------------------------

__global__ void k_z() {
    int v = blockIdx.x * (blockDim.x >> 5) + (threadIdx.x >> 5);
    if (v >= NN) return;
    int lane = threadIdx.x & 31;
    float4 h = unpack4h(g_hs[(size_t)v * 32 + lane]);
    float4 q = ((const float4*)g_q)[lane];
    float4 q2 = ((const float4*)g_q2)[lane];
    float z  = h.x * q.x  + h.y * q.y  + h.z * q.z  + h.w * q.w;
    float z2 = h.x * q2.x + h.y * q2.y + h.z * q2.z + h.w * q2.w;
    #pragma unroll
    for (int off = 16; off; off >>= 1) {
        z  += __shfl_xor_sync(0xffffffff, z,  off);
        z2 += __shfl_xor_sync(0xffffffff, z2, off);
    }
    if (lane == 0) g_zz[v] = make_float2(z, z2);
}

__global__ void k_zagg(float* __restrict__ out) {
    __shared__ float red[256];
    int v = blockIdx.x * blockDim.x + threadIdx.x;
    float vp = 0.f;
    if (v < NN) {
        int beg = g_rowptr[v], end = g_rowptr[v + 1];
        float s0 = 0.f, s1 = 0.f, t0 = 0.f, t1 = 0.f;
        int e = beg;
        for (; e + 1 < end; e += 2) {
            float2 a = g_zz[g_esrc[e]];
            float2 b = g_zz[g_esrc[e + 1]];
            s0 += a.x; t0 += a.y;
            s1 += b.x; t1 += b.y;
        }
        if (e < end) {
            float2 a = g_zz[g_esrc[e]];
            s0 += a.x; t0 += a.y;
        }
        float nd = g_ndst[v];
        out[v] = nd * (s0 + s1) + g_cPI;
        vp = nd * (t0 + t1);
    }
    red[threadIdx.x] = vp;
    __syncthreads();
    for (int off = 128; off; off >>= 1) {
        if (threadIdx.x < off) red[threadIdx.x] += red[threadIdx.x + off];
        __syncthreads();
    }
    if (threadIdx.x == 0) atomicAdd(&out[NN], red[0]);
}

// --------------------------- launch ----------------------------------------

extern "C" void kernel_launch(void* const* d_in, const int* in_sizes, int n_in,
                              void* d_out, int out_size) {
    const float* feats = (const float*)d_in[0];
    const int*   src   = (const int*)d_in[1];
    const int*   dst   = (const int*)d_in[2];
    const float* W0 = (const float*)d_in[3];  const float* b0 = (const float*)d_in[4];
    const float* W1 = (const float*)d_in[5];  const float* b1 = (const float*)d_in[6];
    const float* W2 = (const float*)d_in[7];  const float* b2 = (const float*)d_in[8];
    const float* W3 = (const float*)d_in[9];  const float* b3 = (const float*)d_in[10];
    const float* Wp = (const float*)d_in[11]; const float* bp = (const float*)d_in[12];
    const float* Wv = (const float*)d_in[13]; const float* bv = (const float*)d_in[14];
    float* out = (float*)d_out;

    cudaFuncSetAttribute(k_gemm, cudaFuncAttributeMaxDynamicSharedMemorySize,
                         GEMM_SMEM);

    k_zero<<<(NN + 255) / 256, 256>>>();
    k_hist<<<(NE + 255) / 256, 256>>>(src, dst);
    k_scan<<<1, 1024>>>();
    k_norm<<<(NN + 255) / 256, 256>>>();
    k_fill<<<(NE + 255) / 256, 256>>>(src, dst);
    k_prep<<<1, 128>>>(W3, b3, Wp, bp, Wv, bv, out);
    k_scale0<<<(NN * 32 + 255) / 256, 256>>>(feats);

    const int aggGrid  = (NN + 7) / 8;        // 8 warps/block
    const int gemmGrid = (NN + 127) / 128;    // 391

    k_agg<<<aggGrid, 256>>>();
    k_gemm<<<gemmGrid, 256, GEMM_SMEM>>>(W0, b0);
    k_agg<<<aggGrid, 256>>>();
    k_gemm<<<gemmGrid, 256, GEMM_SMEM>>>(W1, b1);
    k_agg<<<aggGrid, 256>>>();
    k_gemm<<<gemmGrid, 256, GEMM_SMEM>>>(W2, b2);

    k_z<<<aggGrid, 256>>>();
    k_zagg<<<(NN + 255) / 256, 256>>>(out);
}

// round 9
// speedup vs baseline: 1.5817x; 1.0928x over previous
#include <cuda_runtime.h>
#include <cuda_fp16.h>
#include <cstdint>

// ---------------------------------------------------------------------------
// GCN, 4 layers + heads. R9:
//  - activations g_hs AND g_agg in fp16; fp32 accumulate everywhere
//  - GEMM: mma.sync m16n8k16 fp16 (A copy-staged, W transposed-staged)
//  - layer-2 GEMM computes z/z2 in-epilogue (k_z deleted)
//  - separate small kernels (merging regressed twice: R5/R6)
// ---------------------------------------------------------------------------

constexpr int NN = 50000;
constexpr int NE = 800000;

__device__ int    g_outdeg[NN];
__device__ int    g_indeg[NN];
__device__ float  g_nsrc[NN];
__device__ float  g_ndst[NN];
__device__ int    g_rowptr[NN + 1];
__device__ int    g_cursor[NN];
__device__ int    g_esrc[NE];
__device__ uint2  g_hs[(size_t)NN * 32];    // fp16 activations (gather source)
__device__ uint2  g_agg[(size_t)NN * 32];   // fp16 aggregated * norm_dst (GEMM A)
__device__ float2 g_zz[NN];                 // (z, z2) per node
__device__ float  g_q[128];                 // W3 @ Wp
__device__ float  g_q2[128];                // W3 @ Wv
__device__ float  g_cPI;

__device__ __forceinline__ void mma_f16(float* c, const uint32_t* a,
                                        uint32_t b0, uint32_t b1) {
    asm("mma.sync.aligned.m16n8k16.row.col.f32.f16.f16.f32 "
        "{%0,%1,%2,%3},{%4,%5,%6,%7},{%8,%9},{%0,%1,%2,%3};"
        : "+f"(c[0]), "+f"(c[1]), "+f"(c[2]), "+f"(c[3])
        : "r"(a[0]), "r"(a[1]), "r"(a[2]), "r"(a[3]), "r"(b0), "r"(b1));
}

__device__ __forceinline__ uint2 pack4h(float4 v) {
    uint2 r;
    __half2 h0 = __floats2half2_rn(v.x, v.y);
    __half2 h1 = __floats2half2_rn(v.z, v.w);
    r.x = *(uint32_t*)&h0;
    r.y = *(uint32_t*)&h1;
    return r;
}
__device__ __forceinline__ float4 unpack4h(uint2 u) {
    __half2 h0 = *(__half2*)&u.x;
    __half2 h1 = *(__half2*)&u.y;
    float2 f0 = __half22float2(h0);
    float2 f1 = __half22float2(h1);
    return make_float4(f0.x, f0.y, f1.x, f1.y);
}

// --------------------------- setup ----------------------------------------

__global__ void k_zero() {
    int i = blockIdx.x * blockDim.x + threadIdx.x;
    if (i < NN) { g_outdeg[i] = 0; g_indeg[i] = 0; }
}

__global__ void k_hist(const int* __restrict__ src, const int* __restrict__ dst) {
    int e = blockIdx.x * blockDim.x + threadIdx.x;
    if (e < NE) {
        atomicAdd(&g_outdeg[src[e]], 1);
        atomicAdd(&g_indeg[dst[e]], 1);
    }
}

__global__ void k_scan() {
    constexpr int CH = (NN + 1023) / 1024;   // 49
    __shared__ int ts[1024];
    int t = threadIdx.x;
    int base = t * CH;
    int s = 0;
    for (int i = 0; i < CH; i++) {
        int idx = base + i;
        int v = (idx < NN) ? g_indeg[idx] : 0;
        if (idx < NN) g_rowptr[idx] = s;
        s += v;
    }
    ts[t] = s;
    __syncthreads();
    for (int off = 1; off < 1024; off <<= 1) {
        int v = (t >= off) ? ts[t - off] : 0;
        __syncthreads();
        ts[t] += v;
        __syncthreads();
    }
    int offset = ts[t] - s;
    for (int i = 0; i < CH; i++) {
        int idx = base + i;
        if (idx < NN) {
            int p = g_rowptr[idx] + offset;
            g_rowptr[idx] = p;
            g_cursor[idx] = p;
        }
    }
    if (t == 1023) g_rowptr[NN] = ts[1023];
}

__global__ void k_norm() {
    int i = blockIdx.x * blockDim.x + threadIdx.x;
    if (i < NN) {
        g_nsrc[i] = rsqrtf((float)max(g_outdeg[i], 1));
        g_ndst[i] = rsqrtf((float)max(g_indeg[i], 1));
    }
}

__global__ void k_fill(const int* __restrict__ src, const int* __restrict__ dst) {
    int e = blockIdx.x * blockDim.x + threadIdx.x;
    if (e < NE) {
        int p = atomicAdd(&g_cursor[dst[e]], 1);
        g_esrc[p] = src[e];
    }
}

__global__ void k_scale0(const float* __restrict__ feats) {
    int i = blockIdx.x * blockDim.x + threadIdx.x;   // float4 index
    constexpr int TOT = NN * 32;
    if (i < TOT) {
        int node = i >> 5;
        float s = g_nsrc[node];
        float4 x = ((const float4*)feats)[i];
        x.x *= s; x.y *= s; x.z *= s; x.w *= s;
        g_hs[i] = pack4h(x);
    }
}

__global__ void k_prep(const float* __restrict__ W3, const float* __restrict__ b3,
                       const float* __restrict__ Wp, const float* __restrict__ bp,
                       const float* __restrict__ Wv, const float* __restrict__ bv,
                       float* __restrict__ out) {
    int k = threadIdx.x;   // 128 threads
    float a = 0.f, c = 0.f;
    for (int j = 0; j < 64; j++) {
        float w = W3[k * 64 + j];
        a += w * Wp[j];
        c += w * Wv[j];
    }
    g_q[k] = a;
    g_q2[k] = c;
    if (k == 0) {
        float cp = 0.f, cv = 0.f;
        for (int j = 0; j < 64; j++) { cp += b3[j] * Wp[j]; cv += b3[j] * Wv[j]; }
        g_cPI = cp + bp[0];
        out[NN] = (float)NN * cv + bv[0];
    }
}

// --------------------------- aggregation ----------------------------------
// One warp per node; lane owns 4 feats (8B fp16). 8-deep edge unroll.
// Output g_agg in fp16.

__global__ void k_agg() {
    int v = blockIdx.x * (blockDim.x >> 5) + (threadIdx.x >> 5);
    if (v >= NN) return;
    int lane = threadIdx.x & 31;
    int beg = g_rowptr[v], end = g_rowptr[v + 1];
    float4 a0 = make_float4(0.f, 0.f, 0.f, 0.f);
    float4 a1 = a0;
    int e = beg;
    for (; e + 7 < end; e += 8) {
        uint2 x[8];
        #pragma unroll
        for (int j = 0; j < 8; j++)
            x[j] = g_hs[(size_t)g_esrc[e + j] * 32 + lane];
        #pragma unroll
        for (int j = 0; j < 8; j += 2) {
            float4 f0 = unpack4h(x[j]);
            float4 f1 = unpack4h(x[j + 1]);
            a0.x += f0.x; a0.y += f0.y; a0.z += f0.z; a0.w += f0.w;
            a1.x += f1.x; a1.y += f1.y; a1.z += f1.z; a1.w += f1.w;
        }
    }
    for (; e < end; e++) {
        float4 f = unpack4h(g_hs[(size_t)g_esrc[e] * 32 + lane]);
        a0.x += f.x; a0.y += f.y; a0.z += f.z; a0.w += f.w;
    }
    float nd = g_ndst[v];
    float4 o;
    o.x = (a0.x + a1.x) * nd;
    o.y = (a0.y + a1.y) * nd;
    o.z = (a0.z + a1.z) * nd;
    o.w = (a0.w + a1.w) * nd;
    g_agg[v * 32 + lane] = pack4h(o);
}

// --------------------------- fp16 tensor-core GEMM -------------------------
// out = relu(g_agg @ W + b) * nsrc; W 128x128 row-major [k][n] fp32 -> fp16.
// Block: 128 rows x 128 cols, 256 threads, mma m16n8k16.
// sA fp16 [row][k] stride 136; sW fp16 [n][k] stride 136 (W transposed).
// TAIL: instead of writing g_hs, compute z = h.q, z2 = h.q2 per row (smem
// atomic row-reduction) and write g_zz.

constexpr int PADH = 136;                          // halves
constexpr int GEMM_SMEM = 2 * 128 * PADH * 2;      // 69632 B

template <bool TAIL>
__global__ void __launch_bounds__(256) k_gemm(const float* __restrict__ W,
                                              const float* __restrict__ bia) {
    extern __shared__ __half smh[];
    __half* sA = smh;                    // [row][k]
    __half* sW = smh + 128 * PADH;       // [n][k]

    int tid  = threadIdx.x;
    int lane = tid & 31;
    int warp = tid >> 5;
    int row0 = blockIdx.x * 128;

    // stage A: copy fp16 rows (4096 uint2)
    #pragma unroll
    for (int it = 0; it < 16; it++) {
        int i = it * 256 + tid;
        int r = i >> 5, c = i & 31;
        int gr = row0 + r;
        uint2 v = (gr < NN) ? g_agg[(size_t)gr * 32 + c] : make_uint2(0u, 0u);
        *(uint2*)&sA[r * PADH + c * 4] = v;
    }
    // stage W transposed: unit = (n, k-quad); coalesced reads of W rows
    #pragma unroll
    for (int it = 0; it < 16; it++) {
        int u = it * 256 + tid;          // 0..4095
        int n = u & 127;
        int k0 = (u >> 7) * 4;           // 0,4,...,124
        float w0 = W[(k0 + 0) * 128 + n];
        float w1 = W[(k0 + 1) * 128 + n];
        float w2 = W[(k0 + 2) * 128 + n];
        float w3 = W[(k0 + 3) * 128 + n];
        uint2 pv = pack4h(make_float4(w0, w1, w2, w3));
        *(uint2*)&sW[n * PADH + k0] = pv;
    }
    __syncthreads();

    int wm = (warp >> 1) * 32;           // warp row offset
    int wn = (warp & 1) * 64;            // warp col offset
    int qr = lane >> 2;                  // 0..7
    int qc = lane & 3;                   // 0..3

    float acc[2][8][4];
    #pragma unroll
    for (int mf = 0; mf < 2; mf++)
        #pragma unroll
        for (int nf = 0; nf < 8; nf++)
            #pragma unroll
            for (int j = 0; j < 4; j++) acc[mf][nf][j] = 0.f;

    #pragma unroll
    for (int ks = 0; ks < 8; ks++) {
        int kb = ks * 16;
        uint32_t a[2][4];
        #pragma unroll
        for (int mf = 0; mf < 2; mf++) {
            int r = wm + mf * 16 + qr;
            a[mf][0] = *(const uint32_t*)&sA[r * PADH + kb + qc * 2];
            a[mf][1] = *(const uint32_t*)&sA[(r + 8) * PADH + kb + qc * 2];
            a[mf][2] = *(const uint32_t*)&sA[r * PADH + kb + 8 + qc * 2];
            a[mf][3] = *(const uint32_t*)&sA[(r + 8) * PADH + kb + 8 + qc * 2];
        }
        #pragma unroll
        for (int nf = 0; nf < 8; nf++) {
            int n = wn + nf * 8 + qr;
            uint32_t b0 = *(const uint32_t*)&sW[n * PADH + kb + qc * 2];
            uint32_t b1 = *(const uint32_t*)&sW[n * PADH + kb + 8 + qc * 2];
            mma_f16(acc[0][nf], a[0], b0, b1);
            mma_f16(acc[1][nf], a[1], b0, b1);
        }
    }

    if (!TAIL) {
        // bias + relu + nsrc -> fp16 g_hs
        #pragma unroll
        for (int mf = 0; mf < 2; mf++) {
            int r0 = row0 + wm + mf * 16 + qr;
            int r1 = r0 + 8;
            float s0 = (r0 < NN) ? g_nsrc[r0] : 0.f;
            float s1 = (r1 < NN) ? g_nsrc[r1] : 0.f;
            #pragma unroll
            for (int nf = 0; nf < 8; nf++) {
                int c = wn + nf * 8 + qc * 2;
                float2 bb = *(const float2*)&bia[c];
                if (r0 < NN) {
                    __half2 h = __floats2half2_rn(
                        fmaxf(acc[mf][nf][0] + bb.x, 0.f) * s0,
                        fmaxf(acc[mf][nf][1] + bb.y, 0.f) * s0);
                    ((__half2*)g_hs)[(size_t)r0 * 64 + (c >> 1)] = h;
                }
                if (r1 < NN) {
                    __half2 h = __floats2half2_rn(
                        fmaxf(acc[mf][nf][2] + bb.x, 0.f) * s1,
                        fmaxf(acc[mf][nf][3] + bb.y, 0.f) * s1);
                    ((__half2*)g_hs)[(size_t)r1 * 64 + (c >> 1)] = h;
                }
            }
        }
    } else {
        // z-fusion: zred[row][{z,z2}] in smem (reuse sA region)
        float* zred = (float*)smh;
        __syncthreads();                 // MMA loads done; safe to reuse
        if (tid < 256) zred[tid] = 0.f;
        __syncthreads();
        #pragma unroll
        for (int mf = 0; mf < 2; mf++) {
            int rl0 = wm + mf * 16 + qr;
            int rl1 = rl0 + 8;
            int r0 = row0 + rl0, r1 = row0 + rl1;
            float s0 = (r0 < NN) ? g_nsrc[r0] : 0.f;
            float s1 = (r1 < NN) ? g_nsrc[r1] : 0.f;
            float zl0 = 0.f, z2l0 = 0.f, zl1 = 0.f, z2l1 = 0.f;
            #pragma unroll
            for (int nf = 0; nf < 8; nf++) {
                int c = wn + nf * 8 + qc * 2;
                float2 bb  = *(const float2*)&bia[c];
                float2 qv  = *(const float2*)&g_q[c];
                float2 qv2 = *(const float2*)&g_q2[c];
                float h00 = fmaxf(acc[mf][nf][0] + bb.x, 0.f) * s0;
                float h01 = fmaxf(acc[mf][nf][1] + bb.y, 0.f) * s0;
                float h10 = fmaxf(acc[mf][nf][2] + bb.x, 0.f) * s1;
                float h11 = fmaxf(acc[mf][nf][3] + bb.y, 0.f) * s1;
                zl0  += h00 * qv.x  + h01 * qv.y;
                z2l0 += h00 * qv2.x + h01 * qv2.y;
                zl1  += h10 * qv.x  + h11 * qv.y;
                z2l1 += h10 * qv2.x + h11 * qv2.y;
            }
            atomicAdd(&zred[rl0 * 2],     zl0);
            atomicAdd(&zred[rl0 * 2 + 1], z2l0);
            atomicAdd(&zred[rl1 * 2],     zl1);
            atomicAdd(&zred[rl1 * 2 + 1], z2l1);
        }
        __syncthreads();
        if (tid < 128 && row0 + tid < NN)
            g_zz[row0 + tid] = make_float2(zred[tid * 2], zred[tid * 2 + 1]);
    }
}

// ---------------------- final edge pass + heads ----------------------------

__global__ void k_zagg(float* __restrict__ out) {
    __shared__ float red[256];
    int v = blockIdx.x * blockDim.x + threadIdx.x;
    float vp = 0.f;
    if (v < NN) {
        int beg = g_rowptr[v], end = g_rowptr[v + 1];
        float s0 = 0.f, s1 = 0.f, t0 = 0.f, t1 = 0.f;
        int e = beg;
        for (; e + 1 < end; e += 2) {
            float2 a = g_zz[g_esrc[e]];
            float2 b = g_zz[g_esrc[e + 1]];
            s0 += a.x; t0 += a.y;
            s1 += b.x; t1 += b.y;
        }
        if (e < end) {
            float2 a = g_zz[g_esrc[e]];
            s0 += a.x; t0 += a.y;
        }
        float nd = g_ndst[v];
        out[v] = nd * (s0 + s1) + g_cPI;
        vp = nd * (t0 + t1);
    }
    red[threadIdx.x] = vp;
    __syncthreads();
    for (int off = 128; off; off >>= 1) {
        if (threadIdx.x < off) red[threadIdx.x] += red[threadIdx.x + off];
        __syncthreads();
    }
    if (threadIdx.x == 0) atomicAdd(&out[NN], red[0]);
}

// --------------------------- launch ----------------------------------------

extern "C" void kernel_launch(void* const* d_in, const int* in_sizes, int n_in,
                              void* d_out, int out_size) {
    const float* feats = (const float*)d_in[0];
    const int*   src   = (const int*)d_in[1];
    const int*   dst   = (const int*)d_in[2];
    const float* W0 = (const float*)d_in[3];  const float* b0 = (const float*)d_in[4];
    const float* W1 = (const float*)d_in[5];  const float* b1 = (const float*)d_in[6];
    const float* W2 = (const float*)d_in[7];  const float* b2 = (const float*)d_in[8];
    const float* W3 = (const float*)d_in[9];  const float* b3 = (const float*)d_in[10];
    const float* Wp = (const float*)d_in[11]; const float* bp = (const float*)d_in[12];
    const float* Wv = (const float*)d_in[13]; const float* bv = (const float*)d_in[14];
    float* out = (float*)d_out;

    cudaFuncSetAttribute(k_gemm<false>, cudaFuncAttributeMaxDynamicSharedMemorySize,
                         GEMM_SMEM);
    cudaFuncSetAttribute(k_gemm<true>, cudaFuncAttributeMaxDynamicSharedMemorySize,
                         GEMM_SMEM);

    k_zero<<<(NN + 255) / 256, 256>>>();
    k_hist<<<(NE + 255) / 256, 256>>>(src, dst);
    k_scan<<<1, 1024>>>();
    k_norm<<<(NN + 255) / 256, 256>>>();
    k_fill<<<(NE + 255) / 256, 256>>>(src, dst);
    k_prep<<<1, 128>>>(W3, b3, Wp, bp, Wv, bv, out);
    k_scale0<<<(NN * 32 + 255) / 256, 256>>>(feats);

    const int aggGrid  = (NN + 7) / 8;        // 8 warps/block
    const int gemmGrid = (NN + 127) / 128;    // 391

    k_agg<<<aggGrid, 256>>>();
    k_gemm<false><<<gemmGrid, 256, GEMM_SMEM>>>(W0, b0);
    k_agg<<<aggGrid, 256>>>();
    k_gemm<false><<<gemmGrid, 256, GEMM_SMEM>>>(W1, b1);
    k_agg<<<aggGrid, 256>>>();
    k_gemm<true><<<gemmGrid, 256, GEMM_SMEM>>>(W2, b2);

    k_zagg<<<(NN + 255) / 256, 256>>>(out);
}